// round 1
// baseline (speedup 1.0000x reference)
#include <cuda_runtime.h>
#include <math.h>

#define T_TOK 8192
#define D_DIM 1024
#define F_DIM 4096
#define E_NUM 8
#define A_TOT (2 * T_TOK)  /* 16384 total (token, expert) assignments */

// ---------------- scratch (no allocation allowed -> device globals) --------
__device__ int   g_counts[E_NUM];
__device__ int   g_offsets[E_NUM + 1];
__device__ int   g_expidx[A_TOT];
__device__ int   g_pos[A_TOT];
__device__ float g_wt[A_TOT];
__device__ int   g_slot[A_TOT];
__device__ int   g_sorted_tok[A_TOT];
__device__ float g_sorted_wt[A_TOT];
__device__ float g_h[(size_t)A_TOT * F_DIM];  // 256 MB: per-assignment hidden acts
__device__ float g_y[(size_t)A_TOT * D_DIM];  // 64 MB: per-assignment outputs

__device__ __forceinline__ float gelu_exact(float v) {
    return 0.5f * v * (1.0f + erff(v * 0.70710678118654752440f));
}

// ---------------------------------------------------------------------------
__global__ void zero_kernel() {
    if (threadIdx.x < E_NUM) g_counts[threadIdx.x] = 0;
}

// Block per token: logits = x[t] @ gate_w, top-2, softmax, atomic expert slot.
__global__ __launch_bounds__(256) void gate_kernel(const float* __restrict__ x,
                                                   const float* __restrict__ gw) {
    __shared__ float red[256][9];
    const int t = blockIdx.x;
    const int tid = threadIdx.x;
    float acc[8] = {0.f, 0.f, 0.f, 0.f, 0.f, 0.f, 0.f, 0.f};
    const float* xr = x + (size_t)t * D_DIM;
    for (int j = tid; j < D_DIM; j += 256) {
        float xv = xr[j];
        const float* g = gw + j * E_NUM;
#pragma unroll
        for (int e = 0; e < 8; e++) acc[e] += xv * g[e];
    }
#pragma unroll
    for (int e = 0; e < 8; e++) red[tid][e] = acc[e];
    __syncthreads();
    for (int s = 128; s > 0; s >>= 1) {
        if (tid < s) {
#pragma unroll
            for (int e = 0; e < 8; e++) red[tid][e] += red[tid + s][e];
        }
        __syncthreads();
    }
    if (tid == 0) {
        float v[8];
#pragma unroll
        for (int e = 0; e < 8; e++) v[e] = red[0][e];
        // top-2 with lowest-index tie-break (matches jax.lax.top_k)
        int i0 = 0;
#pragma unroll
        for (int e = 1; e < 8; e++) if (v[e] > v[i0]) i0 = e;
        int i1 = (i0 == 0) ? 1 : 0;
#pragma unroll
        for (int e = 0; e < 8; e++) if (e != i1 && e != i0 && v[e] > v[i1]) i1 = e;
        // softmax over [v[i0], v[i1]], v[i0] >= v[i1]
        float e1 = __expf(v[i1] - v[i0]);
        // use expf (accurate) instead of __expf for safety
        e1 = expf(v[i1] - v[i0]);
        float inv = 1.0f / (1.0f + e1);
        float w0 = inv;
        float w1 = e1 * inv;
        int p0 = atomicAdd(&g_counts[i0], 1);
        int p1 = atomicAdd(&g_counts[i1], 1);
        g_expidx[2 * t + 0] = i0;
        g_expidx[2 * t + 1] = i1;
        g_pos[2 * t + 0] = p0;
        g_pos[2 * t + 1] = p1;
        g_wt[2 * t + 0] = w0;
        g_wt[2 * t + 1] = w1;
    }
}

__global__ void scan_kernel() {
    if (threadIdx.x == 0) {
        int s = 0;
#pragma unroll
        for (int e = 0; e < E_NUM; e++) { g_offsets[e] = s; s += g_counts[e]; }
        g_offsets[E_NUM] = s;
    }
}

__global__ void scatter_kernel() {
    int i = blockIdx.x * 256 + threadIdx.x;
    if (i >= A_TOT) return;
    int e = g_expidx[i];
    int s = g_offsets[e] + g_pos[i];
    g_slot[i] = s;
    g_sorted_tok[s] = i >> 1;
    g_sorted_wt[s] = g_wt[i];
}

// ---------------- grouped GEMM1: h = gelu(x_gather @ w1[e] + b1[e]) --------
// Tile 64(M) x 64(N) x 16(K), 256 threads, 4x4 per thread. fp32.
__global__ __launch_bounds__(256) void ffn1_kernel(const float* __restrict__ x,
                                                   const float* __restrict__ w1,
                                                   const float* __restrict__ b1) {
    const int e = blockIdx.z;
    const int cnt = g_counts[e];
    const int m0 = blockIdx.y * 64;
    if (m0 >= cnt) return;
    const int off = g_offsets[e];
    const int n0 = blockIdx.x * 64;

    __shared__ float As[64][17];
    __shared__ __align__(16) float Bs[16][64];
    __shared__ int toks[64];

    const int tid = threadIdx.x;
    if (tid < 64) {
        int m = m0 + tid;
        toks[tid] = g_sorted_tok[off + (m < cnt ? m : cnt - 1)];
    }
    __syncthreads();

    const int arow = tid >> 2;          // 0..63 (M row in tile)
    const int akq = (tid & 3) << 2;     // 0,4,8,12 (K quad)
    const int brow = tid >> 4;          // 0..15 (K row)
    const int bcol = (tid & 15) << 2;   // 0..60 (N quad)
    const int tx = tid & 15;
    const int ty = tid >> 4;

    const float* Ap = x + (size_t)toks[arow] * D_DIM + akq;
    const float* Bp = w1 + (size_t)e * D_DIM * F_DIM + (size_t)brow * F_DIM + n0 + bcol;

    float acc[4][4] = {};

    for (int k0 = 0; k0 < D_DIM; k0 += 16) {
        float4 av = *(const float4*)(Ap + k0);
        float4 bv = *(const float4*)(Bp + (size_t)k0 * F_DIM);
        As[arow][akq + 0] = av.x;
        As[arow][akq + 1] = av.y;
        As[arow][akq + 2] = av.z;
        As[arow][akq + 3] = av.w;
        *(float4*)&Bs[brow][bcol] = bv;
        __syncthreads();
#pragma unroll
        for (int kk = 0; kk < 16; kk++) {
            float a0 = As[ty * 4 + 0][kk];
            float a1 = As[ty * 4 + 1][kk];
            float a2 = As[ty * 4 + 2][kk];
            float a3 = As[ty * 4 + 3][kk];
            float4 b4 = *(const float4*)&Bs[kk][tx * 4];
            acc[0][0] += a0 * b4.x; acc[0][1] += a0 * b4.y; acc[0][2] += a0 * b4.z; acc[0][3] += a0 * b4.w;
            acc[1][0] += a1 * b4.x; acc[1][1] += a1 * b4.y; acc[1][2] += a1 * b4.z; acc[1][3] += a1 * b4.w;
            acc[2][0] += a2 * b4.x; acc[2][1] += a2 * b4.y; acc[2][2] += a2 * b4.z; acc[2][3] += a2 * b4.w;
            acc[3][0] += a3 * b4.x; acc[3][1] += a3 * b4.y; acc[3][2] += a3 * b4.z; acc[3][3] += a3 * b4.w;
        }
        __syncthreads();
    }

    const int n = n0 + tx * 4;
    float4 bb = *(const float4*)(b1 + (size_t)e * F_DIM + n);
#pragma unroll
    for (int i = 0; i < 4; i++) {
        int m = m0 + ty * 4 + i;
        if (m >= cnt) continue;
        size_t s = (size_t)(off + m);
        float4 r;
        r.x = gelu_exact(acc[i][0] + bb.x);
        r.y = gelu_exact(acc[i][1] + bb.y);
        r.z = gelu_exact(acc[i][2] + bb.z);
        r.w = gelu_exact(acc[i][3] + bb.w);
        *(float4*)(g_h + s * F_DIM + n) = r;
    }
}

// ---------------- grouped GEMM2: y = wt * (h @ w2[e] + b2[e]) --------------
__global__ __launch_bounds__(256) void ffn2_kernel(const float* __restrict__ w2,
                                                   const float* __restrict__ b2) {
    const int e = blockIdx.z;
    const int cnt = g_counts[e];
    const int m0 = blockIdx.y * 64;
    if (m0 >= cnt) return;
    const int off = g_offsets[e];
    const int n0 = blockIdx.x * 64;

    __shared__ float As[64][17];
    __shared__ __align__(16) float Bs[16][64];

    const int tid = threadIdx.x;
    const int arow = tid >> 2;
    const int akq = (tid & 3) << 2;
    const int brow = tid >> 4;
    const int bcol = (tid & 15) << 2;
    const int tx = tid & 15;
    const int ty = tid >> 4;

    int mA = m0 + arow;
    int sA = off + (mA < cnt ? mA : cnt - 1);
    const float* Ap = g_h + (size_t)sA * F_DIM + akq;
    const float* Bp = w2 + (size_t)e * F_DIM * D_DIM + (size_t)brow * D_DIM + n0 + bcol;

    float acc[4][4] = {};

    for (int k0 = 0; k0 < F_DIM; k0 += 16) {
        float4 av = *(const float4*)(Ap + k0);
        float4 bv = *(const float4*)(Bp + (size_t)k0 * D_DIM);
        As[arow][akq + 0] = av.x;
        As[arow][akq + 1] = av.y;
        As[arow][akq + 2] = av.z;
        As[arow][akq + 3] = av.w;
        *(float4*)&Bs[brow][bcol] = bv;
        __syncthreads();
#pragma unroll
        for (int kk = 0; kk < 16; kk++) {
            float a0 = As[ty * 4 + 0][kk];
            float a1 = As[ty * 4 + 1][kk];
            float a2 = As[ty * 4 + 2][kk];
            float a3 = As[ty * 4 + 3][kk];
            float4 b4 = *(const float4*)&Bs[kk][tx * 4];
            acc[0][0] += a0 * b4.x; acc[0][1] += a0 * b4.y; acc[0][2] += a0 * b4.z; acc[0][3] += a0 * b4.w;
            acc[1][0] += a1 * b4.x; acc[1][1] += a1 * b4.y; acc[1][2] += a1 * b4.z; acc[1][3] += a1 * b4.w;
            acc[2][0] += a2 * b4.x; acc[2][1] += a2 * b4.y; acc[2][2] += a2 * b4.z; acc[2][3] += a2 * b4.w;
            acc[3][0] += a3 * b4.x; acc[3][1] += a3 * b4.y; acc[3][2] += a3 * b4.z; acc[3][3] += a3 * b4.w;
        }
        __syncthreads();
    }

    const int n = n0 + tx * 4;
    float4 bb = *(const float4*)(b2 + (size_t)e * D_DIM + n);
#pragma unroll
    for (int i = 0; i < 4; i++) {
        int m = m0 + ty * 4 + i;
        if (m >= cnt) continue;
        size_t s = (size_t)(off + m);
        float wt = g_sorted_wt[s];
        float4 r;
        r.x = wt * (acc[i][0] + bb.x);
        r.y = wt * (acc[i][1] + bb.y);
        r.z = wt * (acc[i][2] + bb.z);
        r.w = wt * (acc[i][3] + bb.w);
        *(float4*)(g_y + s * D_DIM + n) = r;
    }
}

// out[t, d] = y[slot0(t), d] + y[slot1(t), d]
__global__ __launch_bounds__(256) void combine_kernel(float* __restrict__ out) {
    int i = blockIdx.x * 256 + threadIdx.x;  // T*D = 8388608 fits int
    int t = i >> 10;
    int d = i & 1023;
    int s0 = g_slot[2 * t + 0];
    int s1 = g_slot[2 * t + 1];
    out[i] = g_y[(size_t)s0 * D_DIM + d] + g_y[(size_t)s1 * D_DIM + d];
}

// ---------------------------------------------------------------------------
extern "C" void kernel_launch(void* const* d_in, const int* in_sizes, int n_in,
                              void* d_out, int out_size) {
    const float* x  = (const float*)d_in[0];
    const float* gw = (const float*)d_in[1];
    const float* w1 = (const float*)d_in[2];
    const float* b1 = (const float*)d_in[3];
    const float* w2 = (const float*)d_in[4];
    const float* b2 = (const float*)d_in[5];
    float* out = (float*)d_out;

    zero_kernel<<<1, 32>>>();
    gate_kernel<<<T_TOK, 256>>>(x, gw);
    scan_kernel<<<1, 32>>>();
    scatter_kernel<<<A_TOT / 256, 256>>>();
    // Oversized static grids (graph-capturable); blocks early-exit on counts.
    ffn1_kernel<<<dim3(F_DIM / 64, T_TOK / 64, E_NUM), 256>>>(x, w1, b1);
    ffn2_kernel<<<dim3(D_DIM / 64, T_TOK / 64, E_NUM), 256>>>(w2, b2);
    combine_kernel<<<(T_TOK * D_DIM) / 256, 256>>>(out);
}

// round 3
// speedup vs baseline: 2.0823x; 2.0823x over previous
#include <cuda_runtime.h>
#include <math.h>
#include <stdint.h>

#define T_TOK 8192
#define D_DIM 1024
#define F_DIM 4096
#define E_NUM 8
#define A_TOT (2 * T_TOK)  /* 16384 (token, expert) assignments */

// ---------------- scratch (no allocation allowed -> device globals) --------
__device__ int   g_counts[E_NUM];
__device__ int   g_offsets[E_NUM + 1];
__device__ int   g_expidx[A_TOT];
__device__ int   g_pos[A_TOT];
__device__ float g_wt[A_TOT];
__device__ int   g_slot[A_TOT];
__device__ int   g_sorted_tok[A_TOT];
__device__ float g_sorted_wt[A_TOT];
__device__ float g_h[(size_t)A_TOT * F_DIM];              // 256 MB hidden acts (tf32-rounded)
__device__ float g_y[(size_t)A_TOT * D_DIM];              // 64 MB per-assignment outputs
__device__ float g_w1t[(size_t)E_NUM * F_DIM * D_DIM];    // 128 MB: w1^T [e][n(F)][k(D)], tf32
__device__ float g_w2t[(size_t)E_NUM * D_DIM * F_DIM];    // 128 MB: w2^T [e][n(D)][k(F)], tf32

__device__ __forceinline__ float to_tf32(float v) {
    float r;
    asm("cvt.rna.tf32.f32 %0, %1;" : "=f"(r) : "f"(v));
    return r;
}

__device__ __forceinline__ float gelu_exact(float v) {
    return 0.5f * v * (1.0f + erff(v * 0.70710678118654752440f));
}

// m16n8k8 tf32 mma: C[16x8] += A[16x8] * B[8x8]
__device__ __forceinline__ void mma_tf32(float* c, const uint32_t* a,
                                         uint32_t b0, uint32_t b1) {
    asm volatile(
        "mma.sync.aligned.m16n8k8.row.col.f32.tf32.tf32.f32 "
        "{%0,%1,%2,%3}, {%4,%5,%6,%7}, {%8,%9}, {%0,%1,%2,%3};"
        : "+f"(c[0]), "+f"(c[1]), "+f"(c[2]), "+f"(c[3])
        : "r"(a[0]), "r"(a[1]), "r"(a[2]), "r"(a[3]), "r"(b0), "r"(b1));
}

// ---------------------------------------------------------------------------
__global__ void zero_kernel() {
    if (threadIdx.x < E_NUM) g_counts[threadIdx.x] = 0;
}

__global__ __launch_bounds__(256) void gate_kernel(const float* __restrict__ x,
                                                   const float* __restrict__ gw) {
    __shared__ float red[256][9];
    const int t = blockIdx.x;
    const int tid = threadIdx.x;
    float acc[8] = {0.f, 0.f, 0.f, 0.f, 0.f, 0.f, 0.f, 0.f};
    const float* xr = x + (size_t)t * D_DIM;
    for (int j = tid; j < D_DIM; j += 256) {
        float xv = xr[j];
        const float* g = gw + j * E_NUM;
#pragma unroll
        for (int e = 0; e < 8; e++) acc[e] += xv * g[e];
    }
#pragma unroll
    for (int e = 0; e < 8; e++) red[tid][e] = acc[e];
    __syncthreads();
    for (int s = 128; s > 0; s >>= 1) {
        if (tid < s) {
#pragma unroll
            for (int e = 0; e < 8; e++) red[tid][e] += red[tid + s][e];
        }
        __syncthreads();
    }
    if (tid == 0) {
        float v[8];
#pragma unroll
        for (int e = 0; e < 8; e++) v[e] = red[0][e];
        int i0 = 0;
#pragma unroll
        for (int e = 1; e < 8; e++) if (v[e] > v[i0]) i0 = e;
        int i1 = (i0 == 0) ? 1 : 0;
#pragma unroll
        for (int e = 0; e < 8; e++) if (e != i1 && e != i0 && v[e] > v[i1]) i1 = e;
        float e1 = expf(v[i1] - v[i0]);
        float inv = 1.0f / (1.0f + e1);
        int p0 = atomicAdd(&g_counts[i0], 1);
        int p1 = atomicAdd(&g_counts[i1], 1);
        g_expidx[2 * t + 0] = i0;
        g_expidx[2 * t + 1] = i1;
        g_pos[2 * t + 0] = p0;
        g_pos[2 * t + 1] = p1;
        g_wt[2 * t + 0] = inv;
        g_wt[2 * t + 1] = e1 * inv;
    }
}

__global__ void scan_kernel() {
    if (threadIdx.x == 0) {
        int s = 0;
#pragma unroll
        for (int e = 0; e < E_NUM; e++) { g_offsets[e] = s; s += g_counts[e]; }
        g_offsets[E_NUM] = s;
    }
}

__global__ void scatter_kernel() {
    int i = blockIdx.x * 256 + threadIdx.x;
    if (i >= A_TOT) return;
    int e = g_expidx[i];
    int s = g_offsets[e] + g_pos[i];
    g_slot[i] = s;
    g_sorted_tok[s] = i >> 1;
    g_sorted_wt[s] = g_wt[i];
}

// Transpose per-expert [R][C] -> [C][R], rounding to tf32.
__global__ __launch_bounds__(256) void transpose_kernel(const float* __restrict__ src,
                                                        float* __restrict__ dst,
                                                        int R, int C) {
    __shared__ float tile[32][33];
    const int e = blockIdx.z;
    src += (size_t)e * R * C;
    dst += (size_t)e * R * C;
    const int c0 = blockIdx.x * 32;
    const int r0 = blockIdx.y * 32;
    const int tx = threadIdx.x;  // 32
    const int ty = threadIdx.y;  // 8
#pragma unroll
    for (int i = 0; i < 4; i++) {
        int r = r0 + ty + i * 8;
        tile[ty + i * 8][tx] = src[(size_t)r * C + c0 + tx];
    }
    __syncthreads();
#pragma unroll
    for (int i = 0; i < 4; i++) {
        int c = c0 + ty + i * 8;
        dst[(size_t)c * R + r0 + tx] = to_tf32(tile[tx][ty + i * 8]);
    }
}

// ---------------- mma.sync tf32 grouped GEMM --------------------------------
// CTA tile 128(M) x 128(N), K chunks of 16. 8 warps as 4(M) x 2(N), warp tile
// 32x64. Fragment-major smem: each thread's mma operands are one LDS.128.
// A frag buffer: fa[s(2)][mb(8)][lane(32)][4]  (8 KB per buffer)
// B frag buffer: fb[s(2)][pair(8)][lane(32)][4] (8 KB per buffer)
// FFN1: A = x rows gathered via g_sorted_tok, tf32-rounded at stage;
//       epi = to_tf32(gelu(acc + b1)) -> g_h
// FFN2: A = g_h rows (already tf32-valued); epi = wt*(acc + b2) -> g_y
template<int K_TOTAL, int FFN1>
__global__ __launch_bounds__(256, 2)
void ffn_mma(const float* __restrict__ Abase,
             const float* __restrict__ wT,
             const float* __restrict__ bias,
             float* __restrict__ out,
             int out_n) {
    const int e = blockIdx.z;
    const int cnt = g_counts[e];
    const int m0 = blockIdx.y * 128;
    if (m0 >= cnt) return;
    const int off = g_offsets[e];
    const int n0 = blockIdx.x * 128;

    __shared__ __align__(16) float fa[2][2048];
    __shared__ __align__(16) float fb[2][2048];
    __shared__ int toks[128];

    const int tid = threadIdx.x;
    const int wid = tid >> 5;
    const int lane = tid & 31;
    const int warp_m = wid >> 1;   // 0..3
    const int warp_n = wid & 1;    // 0..1

    if (tid < 128) {
        int m = m0 + tid;
        if (m >= cnt) m = cnt - 1;
        toks[tid] = FFN1 ? g_sorted_tok[off + m] : (off + m);
    }
    __syncthreads();

    const float* Bsrc = wT + ((size_t)e * out_n + n0) * K_TOTAL;

    // Staging indices for this thread's two float4 loads (A and B each).
    // f = tid + i*256 in [0,512): row = f>>2, k-quad u4 = f&3.
    int s_row[2], s_s[2], s_lb[2], s_slotA[2], s_slotB[2], s_pa[2], s_pb[2];
#pragma unroll
    for (int i = 0; i < 2; i++) {
        int f = tid + i * 256;
        int row = f >> 2;
        int u4 = f & 3;
        int ss = u4 >> 1;
        int uu = u4 & 1;
        int blk = row >> 4;       // mb or pair index (0..7)
        int hh = row & 15;
        s_row[i] = row;
        s_s[i] = u4;              // k-quad within chunk (k = u4*4)
        s_lb[i] = (hh & 7) * 4;   // lane base
        s_slotA[i] = (hh >> 3) + 2 * uu;
        s_slotB[i] = (hh >> 3) * 2 + uu;
        s_pa[i] = ((ss * 8 + blk) * 32 + s_lb[i]) * 4 + s_slotA[i];
        s_pb[i] = ((ss * 8 + blk) * 32 + s_lb[i]) * 4 + s_slotB[i];
    }

    float c[2][8][4];
#pragma unroll
    for (int mi = 0; mi < 2; mi++)
#pragma unroll
        for (int ni = 0; ni < 8; ni++)
#pragma unroll
            for (int j = 0; j < 4; j++) c[mi][ni][j] = 0.0f;

    constexpr int NCHUNK = K_TOTAL / 16;
    float4 ra[2], rb[2];

    // Prologue: load + stage chunk 0.
#pragma unroll
    for (int i = 0; i < 2; i++) {
        ra[i] = *(const float4*)(Abase + (size_t)toks[s_row[i]] * K_TOTAL + s_s[i] * 4);
        rb[i] = *(const float4*)(Bsrc + (size_t)s_row[i] * K_TOTAL + s_s[i] * 4);
    }
#pragma unroll
    for (int i = 0; i < 2; i++) {
        float4 v = ra[i];
        if (FFN1) { v.x = to_tf32(v.x); v.y = to_tf32(v.y); v.z = to_tf32(v.z); v.w = to_tf32(v.w); }
        float* p = &fa[0][s_pa[i]];
        p[0] = v.x; p[4] = v.y; p[8] = v.z; p[12] = v.w;
        float4 w = rb[i];
        float* q = &fb[0][s_pb[i]];
        q[0] = w.x; q[4] = w.y; q[8] = w.z; q[12] = w.w;
    }
    __syncthreads();

    for (int ch = 0; ch < NCHUNK; ch++) {
        const int b = ch & 1;
        const bool more = (ch + 1 < NCHUNK);
        if (more) {
            const int k0 = (ch + 1) * 16;
#pragma unroll
            for (int i = 0; i < 2; i++) {
                ra[i] = *(const float4*)(Abase + (size_t)toks[s_row[i]] * K_TOTAL + k0 + s_s[i] * 4);
                rb[i] = *(const float4*)(Bsrc + (size_t)s_row[i] * K_TOTAL + k0 + s_s[i] * 4);
            }
        }
        // Compute from buffer b.
#pragma unroll
        for (int s = 0; s < 2; s++) {
            uint32_t afr[2][4];
#pragma unroll
            for (int mi = 0; mi < 2; mi++) {
                int mb = warp_m * 2 + mi;
                uint4 v = *(const uint4*)&fa[b][((s * 8 + mb) * 32 + lane) * 4];
                afr[mi][0] = v.x; afr[mi][1] = v.y; afr[mi][2] = v.z; afr[mi][3] = v.w;
            }
            uint32_t bfr[4][4];
#pragma unroll
            for (int pi = 0; pi < 4; pi++) {
                int pb = warp_n * 4 + pi;
                uint4 v = *(const uint4*)&fb[b][((s * 8 + pb) * 32 + lane) * 4];
                bfr[pi][0] = v.x; bfr[pi][1] = v.y; bfr[pi][2] = v.z; bfr[pi][3] = v.w;
            }
#pragma unroll
            for (int mi = 0; mi < 2; mi++)
#pragma unroll
                for (int pi = 0; pi < 4; pi++) {
                    mma_tf32(c[mi][2 * pi + 0], afr[mi], bfr[pi][0], bfr[pi][1]);
                    mma_tf32(c[mi][2 * pi + 1], afr[mi], bfr[pi][2], bfr[pi][3]);
                }
        }
        if (more) {
#pragma unroll
            for (int i = 0; i < 2; i++) {
                float4 v = ra[i];
                if (FFN1) { v.x = to_tf32(v.x); v.y = to_tf32(v.y); v.z = to_tf32(v.z); v.w = to_tf32(v.w); }
                float* p = &fa[b ^ 1][s_pa[i]];
                p[0] = v.x; p[4] = v.y; p[8] = v.z; p[12] = v.w;
                float4 w = rb[i];
                float* q = &fb[b ^ 1][s_pb[i]];
                q[0] = w.x; q[4] = w.y; q[8] = w.z; q[12] = w.w;
            }
        }
        __syncthreads();
    }

    // Epilogue.
    const int g = lane >> 2;
    const int t = lane & 3;
    const float* brow = bias + (size_t)e * out_n + n0;
#pragma unroll
    for (int mi = 0; mi < 2; mi++) {
#pragma unroll
        for (int half = 0; half < 2; half++) {
            int r = (warp_m * 2 + mi) * 16 + g + half * 8;
            int mglob = m0 + r;
            if (mglob >= cnt) continue;
            size_t srow = (size_t)(off + mglob);
            float wt = 1.0f;
            if (!FFN1) wt = g_sorted_wt[srow];
            float* orow = out + srow * (size_t)out_n + n0;
#pragma unroll
            for (int ni = 0; ni < 8; ni++) {
                int col = (warp_n * 8 + ni) * 8 + t * 2;
                float2 bb = *(const float2*)(brow + col);
                float v0 = c[mi][ni][half * 2 + 0] + bb.x;
                float v1 = c[mi][ni][half * 2 + 1] + bb.y;
                float2 o;
                if (FFN1) {
                    o.x = to_tf32(gelu_exact(v0));
                    o.y = to_tf32(gelu_exact(v1));
                } else {
                    o.x = wt * v0;
                    o.y = wt * v1;
                }
                *(float2*)(orow + col) = o;
            }
        }
    }
}

// out[t, d] = y[slot0(t), d] + y[slot1(t), d]
__global__ __launch_bounds__(256) void combine_kernel(float* __restrict__ out) {
    int i = blockIdx.x * 256 + threadIdx.x;
    int t = i >> 10;
    int d = i & 1023;
    int s0 = g_slot[2 * t + 0];
    int s1 = g_slot[2 * t + 1];
    out[i] = g_y[(size_t)s0 * D_DIM + d] + g_y[(size_t)s1 * D_DIM + d];
}

// ---------------------------------------------------------------------------
extern "C" void kernel_launch(void* const* d_in, const int* in_sizes, int n_in,
                              void* d_out, int out_size) {
    const float* x  = (const float*)d_in[0];
    const float* gw = (const float*)d_in[1];
    const float* w1 = (const float*)d_in[2];
    const float* b1 = (const float*)d_in[3];
    const float* w2 = (const float*)d_in[4];
    const float* b2 = (const float*)d_in[5];
    float* out = (float*)d_out;

    float* w1t; cudaGetSymbolAddress((void**)&w1t, g_w1t);
    float* w2t; cudaGetSymbolAddress((void**)&w2t, g_w2t);
    float* hbuf; cudaGetSymbolAddress((void**)&hbuf, g_h);
    float* ybuf; cudaGetSymbolAddress((void**)&ybuf, g_y);

    zero_kernel<<<1, 32>>>();
    gate_kernel<<<T_TOK, 256>>>(x, gw);
    scan_kernel<<<1, 32>>>();
    scatter_kernel<<<A_TOT / 256, 256>>>();

    // w1 [e][D][F] -> w1t [e][F][D]; w2 [e][F][D] -> w2t [e][D][F]  (tf32-rounded)
    transpose_kernel<<<dim3(F_DIM / 32, D_DIM / 32, E_NUM), dim3(32, 8)>>>(w1, w1t, D_DIM, F_DIM);
    transpose_kernel<<<dim3(D_DIM / 32, F_DIM / 32, E_NUM), dim3(32, 8)>>>(w2, w2t, F_DIM, D_DIM);

    // GEMM1: h = gelu(x @ w1 + b1); oversized grid, blocks early-exit on counts.
    ffn_mma<D_DIM, 1><<<dim3(F_DIM / 128, T_TOK / 128, E_NUM), 256>>>(
        x, w1t, b1, hbuf, F_DIM);
    // GEMM2: y = wt * (h @ w2 + b2)
    ffn_mma<F_DIM, 0><<<dim3(D_DIM / 128, T_TOK / 128, E_NUM), 256>>>(
        hbuf, w2t, b2, ybuf, D_DIM);

    combine_kernel<<<(T_TOK * D_DIM) / 256, 256>>>(out);
}